// round 6
// baseline (speedup 1.0000x reference)
#include <cuda_runtime.h>
#include <cstdint>

// Problem constants
#define F_DENSE  13
#define F_SPARSE 26
#define NF       39          // F_DENSE + F_SPARSE
#define E_DIM    16
#define VOC      100000
#define H1       512
#define H2       256
#define D_IN     624         // (13+26)*16

#define THREADS       128
#define WARPS         4
#define SMP_PER_WARP  2
#define SMP_PER_BLOCK 8      // 4 warps * 2 samples

// smem row-buffer geometry (bytes)
#define SLOT_BYTES    128                    // 2 tables * 64B row
#define SAMPLE_STRIDE (F_SPARSE * SLOT_BYTES + 64)   // 3392: +64 pad -> bank-disjoint subs
#define WARP_STRIDE   (SMP_PER_WARP * SAMPLE_STRIDE) // 6784
#define PIECES_PER_SAMPLE (F_SPARSE * 2 * 4)         // 208 x 16B
#define PIECES_PER_WARP   (SMP_PER_WARP * PIECES_PER_SAMPLE) // 416 = 13 rounds * 32 lanes

// Scratch (device globals; no allocation allowed)
__device__ float g_w2eff[H1];
__device__ float g_w1eff[D_IN];
__device__ float g_CONST;

// ---------------------------------------------------------------------------
// Prep 1: w2eff[k] = sum_j Lw2[k,j] * g2[j]
// ---------------------------------------------------------------------------
__global__ void prep_w2eff(const float* __restrict__ Lw2,
                           const float* __restrict__ g2) {
    int w    = (blockIdx.x * blockDim.x + threadIdx.x) >> 5;
    int lane = threadIdx.x & 31;
    if (w >= H1) return;
    float acc = 0.f;
#pragma unroll
    for (int i = 0; i < H2 / 32; i++) {
        int j = lane + i * 32;
        acc = fmaf(__ldg(Lw2 + w * H2 + j), __ldg(g2 + j), acc);
    }
#pragma unroll
    for (int o = 16; o; o >>= 1) acc += __shfl_xor_sync(0xffffffffu, acc, o);
    if (lane == 0) g_w2eff[w] = acc;
}

// ---------------------------------------------------------------------------
// Prep 2: scalar constant
// ---------------------------------------------------------------------------
__global__ void prep_const(const float* __restrict__ Lb1,
                           const float* __restrict__ g1,
                           const float* __restrict__ be1,
                           const float* __restrict__ Lb2,
                           const float* __restrict__ g2,
                           const float* __restrict__ be2) {
    const float inv = rsqrtf(1.f + 1e-5f);
    int k = threadIdx.x;
    float w2e = g_w2eff[k];
    float v = inv * inv * g1[k] * w2e * Lb1[k] + inv * be1[k] * w2e;
    if (k < H2) v += inv * g2[k] * Lb2[k] + be2[k];
    __shared__ float sh[H1];
    sh[k] = v;
    __syncthreads();
    for (int s = H1 / 2; s; s >>= 1) {
        if (k < s) sh[k] += sh[k + s];
        __syncthreads();
    }
    if (k == 0) g_CONST = sh[0];
}

// ---------------------------------------------------------------------------
// Prep 3: w1eff[d] = sum_k Lw1[d,k] * g1[k] * w2eff[k]
// ---------------------------------------------------------------------------
__global__ void prep_w1eff(const float* __restrict__ Lw1,
                           const float* __restrict__ g1) {
    int w    = (blockIdx.x * blockDim.x + threadIdx.x) >> 5;
    int lane = threadIdx.x & 31;
    if (w >= D_IN) return;
    float acc = 0.f;
#pragma unroll
    for (int i = 0; i < H1 / 32; i++) {
        int k = lane + i * 32;
        acc = fmaf(__ldg(Lw1 + w * H1 + k), __ldg(g1 + k) * g_w2eff[k], acc);
    }
#pragma unroll
    for (int o = 16; o; o >>= 1) acc += __shfl_xor_sync(0xffffffffu, acc, o);
    if (lane == 0) g_w1eff[w] = acc;
}

// ---------------------------------------------------------------------------
// Main kernel.
// Phase A: each warp issues 416 x 16B cp.async.cg (its 2 samples' 52 rows),
//          zero destination registers -> cannot be serialized by ptxas,
//          outstanding depth not MSHR/register limited.
// Phase B: consume rows from smem, R1-style 16-lanes-per-sample math.
// ---------------------------------------------------------------------------
__global__ void deepfm_main(
    const int*   __restrict__ Xi,
    const float* __restrict__ Xv,
    const float* __restrict__ W1,
    const float* __restrict__ b1,
    const float* __restrict__ emb1,
    const float* __restrict__ W2,
    const float* __restrict__ b2,
    const float* __restrict__ emb2,
    const float* __restrict__ bias,
    float*       __restrict__ out,
    int n) {
    const float inv2 = 1.f / (1.f + 1e-5f);   // inv^2 = 1/(1+eps)

    __shared__ __align__(16) char  sh_rows[WARPS * WARP_STRIDE]; // 27136 B
    __shared__ int   sh_xi[SMP_PER_BLOCK * NF];
    __shared__ float sh_xv[SMP_PER_BLOCK * NF];

    int tid  = threadIdx.x;
    int base = blockIdx.x * SMP_PER_BLOCK;

    // Stage Xi/Xv (coalesced)
    {
        int gmax = n * NF - base * NF;
        for (int i = tid; i < SMP_PER_BLOCK * NF; i += THREADS) {
            if (i < gmax) {
                sh_xi[i] = Xi[base * NF + i];
                sh_xv[i] = Xv[base * NF + i];
            }
        }
    }
    __syncthreads();

    int lane = tid & 31;
    int warp = tid >> 5;
    uint32_t wbase = (uint32_t)__cvta_generic_to_shared(sh_rows) + warp * WARP_STRIDE;

    // ---- Phase A: async gather of all rows for this warp's 2 samples ----
#pragma unroll
    for (int i = 0; i < PIECES_PER_WARP / 32; i++) {   // 13 rounds
        int r    = i * 32 + lane;                       // 0..415
        int sub  = r / PIECES_PER_SAMPLE;               // 0/1
        int p    = r - sub * PIECES_PER_SAMPLE;         // 0..207
        int slot = p >> 3;                              // 0..25
        int tbl  = (p >> 2) & 1;                        // 0: emb1, 1: emb2
        int q    = p & 3;                               // 16B quarter of the row
        int smp  = warp * SMP_PER_WARP + sub;
        int b    = base + smp;
        if (b < n) {
            int idx = sh_xi[smp * NF + F_DENSE + slot];
            const float* src = (tbl ? emb2 : emb1)
                             + (slot * VOC + idx) * E_DIM + q * 4;
            uint32_t dst = wbase + sub * SAMPLE_STRIDE
                         + slot * SLOT_BYTES + tbl * 64 + q * 16;
            asm volatile("cp.async.cg.shared.global [%0], [%1], 16;\n"
                         :: "r"(dst), "l"(src));
        }
    }
    asm volatile("cp.async.commit_group;\n" ::: "memory");
    asm volatile("cp.async.wait_group 0;\n" ::: "memory");
    __syncwarp();

    // ---- Phase B: consume ----
    int e   = lane & 15;           // embedding column
    int sub = lane >> 4;           // sample within warp
    int smp = warp * SMP_PER_WARP + sub;
    int b   = base + smp;
    bool valid = (b < n);          // no early return: keep shuffles full-warp

    const char*  my   = sh_rows + warp * WARP_STRIDE + sub * SAMPLE_STRIDE;
    const int*   xi   = sh_xi + smp * NF;
    const float* xv   = sh_xv + smp * NF;

    float fm1 = 0.f, se = 0.f, ss = 0.f, hd = 0.f;

#pragma unroll
    for (int s = 0; s < F_SPARSE; s++) {
        float a1 = *(const float*)(my + s * SLOT_BYTES + e * 4);
        float a2 = *(const float*)(my + s * SLOT_BYTES + 64 + e * 4);
        float v  = xv[F_DENSE + s];
        fm1 = fmaf(a1, v, fm1);
        float sev = a2 * v;
        se += sev;
        ss  = fmaf(sev, sev, ss);
        hd  = fmaf(sev, __ldg(g_w1eff + (F_DENSE + s) * E_DIM + e), hd);
    }

    // Dense features (params L1/L2-resident)
#pragma unroll
    for (int f = 0; f < F_DENSE; f++) {
        float x  = (float)xi[f];
        float v  = xv[f];
        int   o  = f * E_DIM + e;
        float sl = fmaf(x, __ldg(W2 + o), __ldg(b2 + o));       // sec_lin
        fm1 = fmaf(fmaf(x, __ldg(W1 + o), __ldg(b1 + o)), v, fm1);
        se += sl;
        ss  = fmaf(sl, sl, ss);
        hd  = fmaf(sl, __ldg(g_w1eff + o), hd);
    }

    float r = fm1 + 0.5f * (se * se - ss) + inv2 * hd;

    // Fold the 16 lanes of this sample (xor<16 stays within half-warp)
#pragma unroll
    for (int o = 1; o < 16; o <<= 1) r += __shfl_xor_sync(0xffffffffu, r, o);

    if (valid && e == 0) out[b] = r + g_CONST + __ldg(bias + b);
}

// ---------------------------------------------------------------------------
extern "C" void kernel_launch(void* const* d_in, const int* in_sizes, int n_in,
                              void* d_out, int out_size) {
    const int*   Xi   = (const int*)  d_in[0];
    const float* Xv   = (const float*)d_in[1];
    const float* W1   = (const float*)d_in[2];
    const float* b1   = (const float*)d_in[3];
    const float* emb1 = (const float*)d_in[4];
    const float* W2   = (const float*)d_in[5];
    const float* b2   = (const float*)d_in[6];
    const float* emb2 = (const float*)d_in[7];
    const float* Lw1  = (const float*)d_in[8];
    const float* Lb1  = (const float*)d_in[9];
    const float* g1   = (const float*)d_in[10];
    const float* be1  = (const float*)d_in[11];
    const float* Lw2  = (const float*)d_in[12];
    const float* Lb2  = (const float*)d_in[13];
    const float* g2   = (const float*)d_in[14];
    const float* be2  = (const float*)d_in[15];
    const float* bias = (const float*)d_in[16];
    float* out = (float*)d_out;

    prep_w2eff<<<(H1 * 32 + 255) / 256, 256>>>(Lw2, g2);
    prep_const<<<1, H1>>>(Lb1, g1, be1, Lb2, g2, be2);
    prep_w1eff<<<(D_IN * 32 + 255) / 256, 256>>>(Lw1, g1);

    int n = out_size;
    int blocks = (n + SMP_PER_BLOCK - 1) / SMP_PER_BLOCK;
    deepfm_main<<<blocks, THREADS>>>(Xi, Xv, W1, b1, emb1, W2, b2, emb2,
                                     bias, out, n);
}

// round 7
// speedup vs baseline: 1.1737x; 1.1737x over previous
#include <cuda_runtime.h>

// Problem constants
#define F_DENSE  13
#define F_SPARSE 26
#define NF       39          // F_DENSE + F_SPARSE
#define E_DIM    16
#define VOC      100000
#define H1       512
#define H2       256
#define D_IN     624         // (13+26)*16

#define THREADS  256

// Scratch (device globals; no allocation allowed)
__device__ float g_w2eff[H1];
__device__ float g_w1eff[D_IN];
__device__ float g_CONST;

// ---------------------------------------------------------------------------
// Prep 1: w2eff[k] = sum_j Lw2[k,j] * g2[j]
// ---------------------------------------------------------------------------
__global__ void prep_w2eff(const float* __restrict__ Lw2,
                           const float* __restrict__ g2) {
    int w    = (blockIdx.x * blockDim.x + threadIdx.x) >> 5;
    int lane = threadIdx.x & 31;
    if (w >= H1) return;
    float acc = 0.f;
#pragma unroll
    for (int i = 0; i < H2 / 32; i++) {
        int j = lane + i * 32;
        acc = fmaf(__ldg(Lw2 + w * H2 + j), __ldg(g2 + j), acc);
    }
#pragma unroll
    for (int o = 16; o; o >>= 1) acc += __shfl_xor_sync(0xffffffffu, acc, o);
    if (lane == 0) g_w2eff[w] = acc;
}

// ---------------------------------------------------------------------------
// Prep 2: scalar constant
// ---------------------------------------------------------------------------
__global__ void prep_const(const float* __restrict__ Lb1,
                           const float* __restrict__ g1,
                           const float* __restrict__ be1,
                           const float* __restrict__ Lb2,
                           const float* __restrict__ g2,
                           const float* __restrict__ be2) {
    const float inv = rsqrtf(1.f + 1e-5f);
    int k = threadIdx.x;
    float w2e = g_w2eff[k];
    float v = inv * inv * g1[k] * w2e * Lb1[k] + inv * be1[k] * w2e;
    if (k < H2) v += inv * g2[k] * Lb2[k] + be2[k];
    __shared__ float sh[H1];
    sh[k] = v;
    __syncthreads();
    for (int s = H1 / 2; s; s >>= 1) {
        if (k < s) sh[k] += sh[k + s];
        __syncthreads();
    }
    if (k == 0) g_CONST = sh[0];
}

// ---------------------------------------------------------------------------
// Prep 3: w1eff[d] = sum_k Lw1[d,k] * g1[k] * w2eff[k]
// ---------------------------------------------------------------------------
__global__ void prep_w1eff(const float* __restrict__ Lw1,
                           const float* __restrict__ g1) {
    int w    = (blockIdx.x * blockDim.x + threadIdx.x) >> 5;
    int lane = threadIdx.x & 31;
    if (w >= D_IN) return;
    float acc = 0.f;
#pragma unroll
    for (int i = 0; i < H1 / 32; i++) {
        int k = lane + i * 32;
        acc = fmaf(__ldg(Lw1 + w * H1 + k), __ldg(g1 + k) * g_w2eff[k], acc);
    }
#pragma unroll
    for (int o = 16; o; o >>= 1) acc += __shfl_xor_sync(0xffffffffu, acc, o);
    if (lane == 0) g_w1eff[w] = acc;
}

// ---------------------------------------------------------------------------
// Batched sparse chunk: CH slots, both tables (2*CH loads in flight).
// Addresses come from pure broadcast __ldg (no smem dependency in front of
// the gathers) — the R1 property that every other variant lost.
// ---------------------------------------------------------------------------
template <int CH>
__device__ __forceinline__ void slots_chunk(
    int c0, const int* __restrict__ xi, const float* __restrict__ xv, int e,
    const float* __restrict__ emb1, const float* __restrict__ emb2,
    float& fm1, float& se, float& ss, float& hd)
{
    int   off[CH];
    float vv[CH];
#pragma unroll
    for (int j = 0; j < CH; j++) {
        int s  = c0 + j;
        int id = __ldg(xi + F_DENSE + s);
        vv[j]  = __ldg(xv + F_DENSE + s);
        off[j] = (s * VOC + id) * E_DIM + e;
    }
    float a1[CH], a2[CH];
#pragma unroll
    for (int j = 0; j < CH; j++) a2[j] = __ldg(emb2 + off[j]);
#pragma unroll
    for (int j = 0; j < CH; j++) a1[j] = __ldg(emb1 + off[j]);
#pragma unroll
    for (int j = 0; j < CH; j++) {
        int s = c0 + j;
        float v   = vv[j];
        float sev = a2[j] * v;
        fm1 = fmaf(a1[j], v, fm1);
        se += sev;
        ss  = fmaf(sev, sev, ss);
        hd  = fmaf(sev, __ldg(g_w1eff + (F_DENSE + s) * E_DIM + e), hd);
    }
}

// ---------------------------------------------------------------------------
// Main kernel: 16 lanes per sample (lane = e), 2 samples per warp,
// 256 threads => 16 samples/block, 1024 blocks (262K threads).
// launch_bounds(256,4): exactly 64 regs -> 32 warps/SM (same occ as R1)
// with room for the 4-slot x 2-table batch (8 loads in flight / thread).
// ---------------------------------------------------------------------------
__global__ __launch_bounds__(THREADS, 4) void deepfm_main(
    const int*   __restrict__ Xi,
    const float* __restrict__ Xv,
    const float* __restrict__ W1,
    const float* __restrict__ b1,
    const float* __restrict__ emb1,
    const float* __restrict__ W2,
    const float* __restrict__ b2,
    const float* __restrict__ emb2,
    const float* __restrict__ bias,
    float*       __restrict__ out,
    int n) {
    const float inv2 = 1.f / (1.f + 1e-5f);   // inv^2 = 1/(1+eps)

    int tid  = threadIdx.x;
    int lane = tid & 31;
    int e    = lane & 15;          // embedding column handled by this lane
    int sub  = lane >> 4;          // 0/1: sample within warp
    int warp = tid >> 5;
    int b    = (blockIdx.x << 4) + (warp << 1) + sub;
    if (b >= n) return;

    const int*   xi = Xi + b * NF;
    const float* xv = Xv + b * NF;

    float fm1 = 0.f;   // first-order sum (partial over this lane's e)
    float se  = 0.f;   // sum_emb[e]
    float ss  = 0.f;   // sumsq[e]
    float hd  = 0.f;   // h . w1eff (partial)

    // Sparse gathers first: 6 chunks of 4 + 1 of 2 (8 loads in flight each)
    slots_chunk<4>( 0, xi, xv, e, emb1, emb2, fm1, se, ss, hd);
    slots_chunk<4>( 4, xi, xv, e, emb1, emb2, fm1, se, ss, hd);
    slots_chunk<4>( 8, xi, xv, e, emb1, emb2, fm1, se, ss, hd);
    slots_chunk<4>(12, xi, xv, e, emb1, emb2, fm1, se, ss, hd);
    slots_chunk<4>(16, xi, xv, e, emb1, emb2, fm1, se, ss, hd);
    slots_chunk<4>(20, xi, xv, e, emb1, emb2, fm1, se, ss, hd);
    slots_chunk<2>(24, xi, xv, e, emb1, emb2, fm1, se, ss, hd);

    // Dense features (all params L1/L2-resident)
#pragma unroll
    for (int f = 0; f < F_DENSE; f++) {
        float x  = (float)__ldg(xi + f);
        float v  = __ldg(xv + f);
        int   o  = f * E_DIM + e;
        float sl = fmaf(x, __ldg(W2 + o), __ldg(b2 + o));       // sec_lin
        fm1 = fmaf(fmaf(x, __ldg(W1 + o), __ldg(b1 + o)), v, fm1);
        se += sl;
        ss  = fmaf(sl, sl, ss);
        hd  = fmaf(sl, __ldg(g_w1eff + o), hd);
    }

    // Per-lane combined partial; fm_second per-e is exact here
    float r = fm1 + 0.5f * (se * se - ss) + inv2 * hd;

    // Fold 16 lanes (xor<16 stays within each half-warp / sample)
#pragma unroll
    for (int o = 1; o < 16; o <<= 1) r += __shfl_xor_sync(0xffffffffu, r, o);

    if (e == 0) out[b] = r + g_CONST + __ldg(bias + b);
}

// ---------------------------------------------------------------------------
extern "C" void kernel_launch(void* const* d_in, const int* in_sizes, int n_in,
                              void* d_out, int out_size) {
    const int*   Xi   = (const int*)  d_in[0];
    const float* Xv   = (const float*)d_in[1];
    const float* W1   = (const float*)d_in[2];
    const float* b1   = (const float*)d_in[3];
    const float* emb1 = (const float*)d_in[4];
    const float* W2   = (const float*)d_in[5];
    const float* b2   = (const float*)d_in[6];
    const float* emb2 = (const float*)d_in[7];
    const float* Lw1  = (const float*)d_in[8];
    const float* Lb1  = (const float*)d_in[9];
    const float* g1   = (const float*)d_in[10];
    const float* be1  = (const float*)d_in[11];
    const float* Lw2  = (const float*)d_in[12];
    const float* Lb2  = (const float*)d_in[13];
    const float* g2   = (const float*)d_in[14];
    const float* be2  = (const float*)d_in[15];
    const float* bias = (const float*)d_in[16];
    float* out = (float*)d_out;

    prep_w2eff<<<(H1 * 32 + 255) / 256, 256>>>(Lw2, g2);
    prep_const<<<1, H1>>>(Lb1, g1, be1, Lb2, g2, be2);
    prep_w1eff<<<(D_IN * 32 + 255) / 256, 256>>>(Lw1, g1);

    int n = out_size;
    int blocks = (n + 15) / 16;
    deepfm_main<<<blocks, THREADS>>>(Xi, Xv, W1, b1, emb1, W2, b2, emb2,
                                     bias, out, n);
}